// round 2
// baseline (speedup 1.0000x reference)
#include <cuda_runtime.h>
#include <math.h>

#define NB   64
#define NT   128
#define NIN  300
#define ND   64
#define NC   10
#define BETAC 0.8f

// ---------------- scratch (device globals; no allocations) ----------------
static __device__ float g_u1r[NB*NT*ND];
static __device__ float g_u1i[NB*NT*ND];
static __device__ float g_L1r[(size_t)NT*NB*ND*ND];   // layer outputs (reused for layer 2)
static __device__ float g_L1i[(size_t)NT*NB*ND*ND];
static __device__ float g_ux2r[(size_t)NT*NB*ND*ND];  // lam * Ux X Ux^T for layer 2
static __device__ float g_ux2i[(size_t)NT*NB*ND*ND];

__device__ __forceinline__ float sigmoidf_(float v) { return 1.0f / (1.0f + expf(-v)); }

#define FMA4(acc, s, v)  do { (acc).x = fmaf((s),(v).x,(acc).x); (acc).y = fmaf((s),(v).y,(acc).y); \
                              (acc).z = fmaf((s),(v).z,(acc).z); (acc).w = fmaf((s),(v).w,(acc).w); } while(0)
#define FMA4N(acc, s, v) do { (acc).x = fmaf(-(s),(v).x,(acc).x); (acc).y = fmaf(-(s),(v).y,(acc).y); \
                              (acc).z = fmaf(-(s),(v).z,(acc).z); (acc).w = fmaf(-(s),(v).w,(acc).w); } while(0)

// ---------------- K1: projections + layer-1 x-side (rank-1) ----------------
// blk = b*NT + t, 64 threads (thread = output dim d)
__global__ void proj_kernel(const float* __restrict__ x,
                            const float* __restrict__ amp_w,
                            const float* __restrict__ amp_b,
                            const float* __restrict__ phase_w,
                            const float* __restrict__ phase_b,
                            const float* __restrict__ Ux)
{
    __shared__ float xsh[NIN];
    __shared__ float red[ND];
    __shared__ float ssr[ND], ssi[ND];
    __shared__ float sUxT[ND*65];   // sUxT[e*65+d] = Ux[d][e]
    const int blk = blockIdx.x;
    const int tid = threadIdx.x;
    const float* xrow = x + (size_t)blk * NIN;

    for (int i = tid; i < NIN; i += ND) xsh[i] = xrow[i];
    for (int i = tid; i < ND*ND; i += ND) sUxT[(i & 63)*65 + (i >> 6)] = Ux[i];
    __syncthreads();

    float a = amp_b[tid], p = phase_b[tid];
#pragma unroll 4
    for (int k = 0; k < NIN; k++) {
        float xv = xsh[k];
        a = fmaf(xv, amp_w[k*ND + tid], a);
        p = fmaf(xv, phase_w[k*ND + tid], p);
    }
    red[tid] = a * a;
    __syncthreads();
    if (tid == 0) {
        float s = 0.f;
        for (int i = 0; i < ND; i++) s += red[i];
        red[0] = 1.0f / sqrtf(s);
    }
    __syncthreads();
    float amp = a * red[0];
    ssr[tid] = amp * cosf(p);
    ssi[tid] = amp * sinf(p);
    __syncthreads();

    float ur = 0.f, ui = 0.f;
#pragma unroll 4
    for (int e = 0; e < ND; e++) {
        float u = sUxT[e*65 + tid];       // Ux[tid][e]
        ur = fmaf(u, ssr[e], ur);
        ui = fmaf(u, ssi[e], ui);
    }
    g_u1r[(size_t)blk*ND + tid] = ur;
    g_u1i[(size_t)blk*ND + tid] = ui;
}

// ---------------- K2/K4: recurrent scan (one CTA per batch element) --------
// MODE 0: layer 1 (x-side = rank-1 outer of g_u1), writes g_L1.
// MODE 1: layer 2 (x-side = g_ux2, lam pre-folded), writes g_L1 (reused).
template<int MODE>
__global__ void __launch_bounds__(256, 1) scan_kernel(const float* __restrict__ Uh,
                                                      const float* __restrict__ lam_ptr)
{
    extern __shared__ float sm[];
    float* sUh  = sm;             // [64][64]
    float* sUhT = sm + 4096;      // sUhT[k*64+j] = Uh[j][k]
    float* sHr  = sm + 8192;
    float* sHi  = sm + 12288;
    float* sTr  = sm + 16384;
    float* sTi  = sm + 20480;
    float* sNr  = sm + 24576;
    float* sNi  = sm + 28672;
    __shared__ float tr_s;
    __shared__ float suvr[ND], suvi[ND];

    const int b   = blockIdx.x;
    const int tid = threadIdx.x;
    const int tx = tid & 15, ty = tid >> 4;
    const int i0 = ty * 4;
    const float lam = sigmoidf_(lam_ptr[0]);
    const float oml = 1.0f - lam;

    for (int i = tid; i < ND*ND; i += 256) {
        float v = Uh[i];
        sUh[i] = v;
        sUhT[(i & 63)*64 + (i >> 6)] = v;
        sHr[i] = ((i >> 6) == (i & 63)) ? (1.0f/ND) : 0.0f;
        sHi[i] = 0.0f;
    }
    __syncthreads();

    for (int t = 0; t < NT; t++) {
        if (MODE == 0) {
            if (tid < ND) {
                suvr[tid] = g_u1r[((size_t)b*NT + t)*ND + tid];
                suvi[tid] = g_u1i[((size_t)b*NT + t)*ND + tid];
            }
        }
        // ---- P1: tmp = Uh @ H (both real and imag share A=Uh) ----
        {
            float4 aR[4], aI[4];
#pragma unroll
            for (int r = 0; r < 4; r++) { aR[r] = make_float4(0,0,0,0); aI[r] = make_float4(0,0,0,0); }
            const float4* hr4 = (const float4*)sHr;
            const float4* hi4 = (const float4*)sHi;
#pragma unroll 4
            for (int k = 0; k < ND; k++) {
                float4 br = hr4[k*16 + tx];
                float4 bi = hi4[k*16 + tx];
#pragma unroll
                for (int r = 0; r < 4; r++) {
                    float av = sUh[(i0+r)*64 + k];
                    FMA4(aR[r], av, br);
                    FMA4(aI[r], av, bi);
                }
            }
#pragma unroll
            for (int r = 0; r < 4; r++) {
                ((float4*)sTr)[(i0+r)*16 + tx] = aR[r];
                ((float4*)sTi)[(i0+r)*16 + tx] = aI[r];
            }
        }
        __syncthreads();

        // ---- P2: UH = tmp @ Uh^T ; N = lam*UX + (1-lam)*UH ----
        {
            float4 nR[4], nI[4];
#pragma unroll
            for (int r = 0; r < 4; r++) { nR[r] = make_float4(0,0,0,0); nI[r] = make_float4(0,0,0,0); }
            const float4* uhT4 = (const float4*)sUhT;
#pragma unroll 4
            for (int k = 0; k < ND; k++) {
                float4 b4 = uhT4[k*16 + tx];
#pragma unroll
                for (int r = 0; r < 4; r++) {
                    float ar = sTr[(i0+r)*64 + k];
                    float ai = sTi[(i0+r)*64 + k];
                    FMA4(nR[r], ar, b4);
                    FMA4(nI[r], ai, b4);
                }
            }
            if (MODE == 0) {
                const int j0 = tx * 4;
                float vjr0 = suvr[j0], vjr1 = suvr[j0+1], vjr2 = suvr[j0+2], vjr3 = suvr[j0+3];
                float vji0 = suvi[j0], vji1 = suvi[j0+1], vji2 = suvi[j0+2], vji3 = suvi[j0+3];
#pragma unroll
                for (int r = 0; r < 4; r++) {
                    float uir = suvr[i0+r], uii = suvi[i0+r];
                    nR[r].x = fmaf(oml, nR[r].x, lam*(uir*vjr0 + uii*vji0));
                    nR[r].y = fmaf(oml, nR[r].y, lam*(uir*vjr1 + uii*vji1));
                    nR[r].z = fmaf(oml, nR[r].z, lam*(uir*vjr2 + uii*vji2));
                    nR[r].w = fmaf(oml, nR[r].w, lam*(uir*vjr3 + uii*vji3));
                    nI[r].x = fmaf(oml, nI[r].x, lam*(uii*vjr0 - uir*vji0));
                    nI[r].y = fmaf(oml, nI[r].y, lam*(uii*vjr1 - uir*vji1));
                    nI[r].z = fmaf(oml, nI[r].z, lam*(uii*vjr2 - uir*vji2));
                    nI[r].w = fmaf(oml, nI[r].w, lam*(uii*vjr3 - uir*vji3));
                }
            } else {
                const float4* xr4 = (const float4*)(g_ux2r + ((size_t)t*NB + b)*4096);
                const float4* xi4 = (const float4*)(g_ux2i + ((size_t)t*NB + b)*4096);
#pragma unroll
                for (int r = 0; r < 4; r++) {
                    float4 xr = xr4[(i0+r)*16 + tx];
                    float4 xi = xi4[(i0+r)*16 + tx];
                    nR[r].x = fmaf(oml, nR[r].x, xr.x);
                    nR[r].y = fmaf(oml, nR[r].y, xr.y);
                    nR[r].z = fmaf(oml, nR[r].z, xr.z);
                    nR[r].w = fmaf(oml, nR[r].w, xr.w);
                    nI[r].x = fmaf(oml, nI[r].x, xi.x);
                    nI[r].y = fmaf(oml, nI[r].y, xi.y);
                    nI[r].z = fmaf(oml, nI[r].z, xi.z);
                    nI[r].w = fmaf(oml, nI[r].w, xi.w);
                }
            }
#pragma unroll
            for (int r = 0; r < 4; r++) {
                ((float4*)sNr)[(i0+r)*16 + tx] = nR[r];
                ((float4*)sNi)[(i0+r)*16 + tx] = nI[r];
            }
        }
        if (tid == 0) tr_s = 0.0f;
        __syncthreads();

        // ---- P3: r2 = N_r N_r - N_i N_i ; i2 = N_r N_i + N_i N_r ; activation ----
        {
            float4 cR[4], cI[4];
#pragma unroll
            for (int r = 0; r < 4; r++) { cR[r] = make_float4(0,0,0,0); cI[r] = make_float4(0,0,0,0); }
            const float4* nr4 = (const float4*)sNr;
            const float4* ni4 = (const float4*)sNi;
#pragma unroll 2
            for (int k = 0; k < ND; k++) {
                float4 br = nr4[k*16 + tx];
                float4 bi = ni4[k*16 + tx];
#pragma unroll
                for (int r = 0; r < 4; r++) {
                    float ar = sNr[(i0+r)*64 + k];
                    float ai = sNi[(i0+r)*64 + k];
                    FMA4 (cR[r], ar, br);
                    FMA4N(cR[r], ai, bi);
                    FMA4 (cI[r], ar, bi);
                    FMA4 (cI[r], ai, br);
                }
            }
            if (ty == tx)  // this thread holds 4 diagonal elements of r2
                atomicAdd(&tr_s, cR[0].x + cR[1].y + cR[2].z + cR[3].w);
            __syncthreads();

            const float s  = BETAC / tr_s;
            const float ob = 1.0f - BETAC;
            float4* gr = (float4*)(g_L1r + ((size_t)t*NB + b)*4096);
            float4* gi = (float4*)(g_L1i + ((size_t)t*NB + b)*4096);
#pragma unroll
            for (int r = 0; r < 4; r++) {
                float4 nr = ((const float4*)sNr)[(i0+r)*16 + tx];
                float4 ni = ((const float4*)sNi)[(i0+r)*16 + tx];
                float4 hR, hI;
                hR.x = fmaf(s, cR[r].x, ob*nr.x);  hR.y = fmaf(s, cR[r].y, ob*nr.y);
                hR.z = fmaf(s, cR[r].z, ob*nr.z);  hR.w = fmaf(s, cR[r].w, ob*nr.w);
                hI.x = fmaf(s, cI[r].x, ob*ni.x);  hI.y = fmaf(s, cI[r].y, ob*ni.y);
                hI.z = fmaf(s, cI[r].z, ob*ni.z);  hI.w = fmaf(s, cI[r].w, ob*ni.w);
                ((float4*)sHr)[(i0+r)*16 + tx] = hR;
                ((float4*)sHi)[(i0+r)*16 + tx] = hI;
                gr[(i0+r)*16 + tx] = hR;
                gi[(i0+r)*16 + tx] = hI;
            }
        }
        __syncthreads();
    }
}

// ---------------- K3: layer-2 x-side conjugation (parallel over t,b) -------
// out = lam * Ux @ X @ Ux^T ; blk = t*NB + b
__global__ void __launch_bounds__(256) uxconj_kernel(const float* __restrict__ Ux,
                                                     const float* __restrict__ lam_ptr)
{
    extern __shared__ float sm[];
    float* sUx  = sm;
    float* sUxT = sm + 4096;
    float* sXr  = sm + 8192;
    float* sXi  = sm + 12288;
    float* sTr  = sm + 16384;
    float* sTi  = sm + 20480;
    const int tid = threadIdx.x;
    const int tx = tid & 15, ty = tid >> 4;
    const int i0 = ty * 4;
    const float lam = sigmoidf_(lam_ptr[0]);
    const size_t base = (size_t)blockIdx.x * 4096;

    for (int i = tid; i < ND*ND; i += 256) {
        float v = Ux[i];
        sUx[i] = v;
        sUxT[(i & 63)*64 + (i >> 6)] = v;
        sXr[i] = g_L1r[base + i];
        sXi[i] = g_L1i[base + i];
    }
    __syncthreads();

    // P1: tmp = Ux @ X
    {
        float4 aR[4], aI[4];
#pragma unroll
        for (int r = 0; r < 4; r++) { aR[r] = make_float4(0,0,0,0); aI[r] = make_float4(0,0,0,0); }
        const float4* xr4 = (const float4*)sXr;
        const float4* xi4 = (const float4*)sXi;
#pragma unroll 4
        for (int k = 0; k < ND; k++) {
            float4 br = xr4[k*16 + tx];
            float4 bi = xi4[k*16 + tx];
#pragma unroll
            for (int r = 0; r < 4; r++) {
                float av = sUx[(i0+r)*64 + k];
                FMA4(aR[r], av, br);
                FMA4(aI[r], av, bi);
            }
        }
#pragma unroll
        for (int r = 0; r < 4; r++) {
            ((float4*)sTr)[(i0+r)*16 + tx] = aR[r];
            ((float4*)sTi)[(i0+r)*16 + tx] = aI[r];
        }
    }
    __syncthreads();

    // P2: out = lam * tmp @ Ux^T
    {
        float4 oR[4], oI[4];
#pragma unroll
        for (int r = 0; r < 4; r++) { oR[r] = make_float4(0,0,0,0); oI[r] = make_float4(0,0,0,0); }
        const float4* uxT4 = (const float4*)sUxT;
#pragma unroll 4
        for (int k = 0; k < ND; k++) {
            float4 b4 = uxT4[k*16 + tx];
#pragma unroll
            for (int r = 0; r < 4; r++) {
                float ar = sTr[(i0+r)*64 + k];
                float ai = sTi[(i0+r)*64 + k];
                FMA4(oR[r], ar, b4);
                FMA4(oI[r], ai, b4);
            }
        }
        float4* gr = (float4*)(g_ux2r + base);
        float4* gi = (float4*)(g_ux2i + base);
#pragma unroll
        for (int r = 0; r < 4; r++) {
            float4 vR = oR[r], vI = oI[r];
            vR.x *= lam; vR.y *= lam; vR.z *= lam; vR.w *= lam;
            vI.x *= lam; vI.y *= lam; vI.z *= lam; vI.w *= lam;
            gr[(i0+r)*16 + tx] = vR;
            gi[(i0+r)*16 + tx] = vI;
        }
    }
}

// ---------------- K5: dense + measurement + log (parallel over t,b) --------
__global__ void __launch_bounds__(256) dense_meas_kernel(const float* __restrict__ W,
                                                         const float* __restrict__ dlam_ptr,
                                                         const float* __restrict__ mk,
                                                         float* __restrict__ out)
{
    __shared__ float sRr[ND*ND], sRi[ND*ND];
    __shared__ float sW[ND*NC];
    __shared__ float tmpr[ND*NC], tmpi[ND*NC];
    __shared__ float sgr[NC*NC], sgi[NC*NC];
    __shared__ float svr[NC*NC], svi[NC*NC];
    const int blk = blockIdx.x;     // t*NB + b
    const int tid = threadIdx.x;
    const size_t base = (size_t)blk * 4096;

    for (int i = tid; i < ND*ND; i += 256) { sRr[i] = g_L1r[base + i]; sRi[i] = g_L1i[base + i]; }
    for (int i = tid; i < ND*NC; i += 256) sW[i] = W[i];
    if (tid < NC) {
        float nrm = 0.f;
        for (int c = 0; c < NC; c++) {
            float vr = mk[(tid*NC + c)*2 + 0];
            float vi = mk[(tid*NC + c)*2 + 1];
            nrm += vr*vr + vi*vi;
        }
        float inv = 1.0f / sqrtf(nrm);
        for (int c = 0; c < NC; c++) {
            svr[tid*NC + c] = mk[(tid*NC + c)*2 + 0] * inv;
            svi[tid*NC + c] = mk[(tid*NC + c)*2 + 1] * inv;
        }
    }
    __syncthreads();

    // tmp = rho @ W  [64][10]
    for (int idx = tid; idx < ND*NC; idx += 256) {
        int d = idx / NC, c = idx % NC;
        float ar = 0.f, ai = 0.f;
#pragma unroll 4
        for (int e = 0; e < ND; e++) {
            float w = sW[e*NC + c];
            ar = fmaf(sRr[d*64 + e], w, ar);
            ai = fmaf(sRi[d*64 + e], w, ai);
        }
        tmpr[idx] = ar; tmpi[idx] = ai;
    }
    __syncthreads();

    // sg = W^T @ tmp [10][10], Lambda-mix
    if (tid < NC*NC) {
        int c = tid / NC, f = tid % NC;
        float ar = 0.f, ai = 0.f;
#pragma unroll 4
        for (int d = 0; d < ND; d++) {
            float w = sW[d*NC + c];
            ar = fmaf(w, tmpr[d*NC + f], ar);
            ai = fmaf(w, tmpi[d*NC + f], ai);
        }
        float dlam = sigmoidf_(dlam_ptr[0]);
        ar = dlam * ar + ((c == f) ? (1.0f - dlam) / NC : 0.0f);
        ai = dlam * ai;
        sgr[tid] = ar; sgi[tid] = ai;
    }
    __syncthreads();

    if (tid < NC) {
        float tr = 0.f;
        for (int c = 0; c < NC; c++) tr += sgr[c*NC + c];
        float invtr = 1.0f / tr;
        int k = tid;
        float p = 0.f;
        for (int c = 0; c < NC; c++) {
            float vrc = svr[k*NC + c], vic = svi[k*NC + c];
            for (int d = 0; d < NC; d++) {
                float vrd = svr[k*NC + d], vid = svi[k*NC + d];
                p += (vrc*vrd + vic*vid) * sgr[c*NC + d]
                   + (vic*vrd - vrc*vid) * sgi[c*NC + d];
            }
        }
        p *= invtr;
        int t = blk / NB, b = blk % NB;
        out[((size_t)b*NT + t)*NC + k] = logf(p);
    }
}

// ---------------- launch ----------------
extern "C" void kernel_launch(void* const* d_in, const int* in_sizes, int n_in,
                              void* d_out, int out_size)
{
    const float* x        = (const float*)d_in[0];
    const float* amp_w    = (const float*)d_in[1];
    const float* amp_b    = (const float*)d_in[2];
    const float* phase_w  = (const float*)d_in[3];
    const float* phase_b  = (const float*)d_in[4];
    const float* Ux       = (const float*)d_in[5];
    const float* Uh       = (const float*)d_in[6];
    const float* cell_l   = (const float*)d_in[7];
    const float* dense_w  = (const float*)d_in[8];
    const float* dense_l  = (const float*)d_in[9];
    const float* meas     = (const float*)d_in[10];
    float* out = (float*)d_out;

    const int SCAN_SMEM = 8 * 4096 * 4;   // 128 KB
    const int UX_SMEM   = 6 * 4096 * 4;   // 96 KB
    cudaFuncSetAttribute(scan_kernel<0>, cudaFuncAttributeMaxDynamicSharedMemorySize, SCAN_SMEM);
    cudaFuncSetAttribute(scan_kernel<1>, cudaFuncAttributeMaxDynamicSharedMemorySize, SCAN_SMEM);
    cudaFuncSetAttribute(uxconj_kernel,  cudaFuncAttributeMaxDynamicSharedMemorySize, UX_SMEM);

    proj_kernel<<<NB*NT, ND>>>(x, amp_w, amp_b, phase_w, phase_b, Ux);
    scan_kernel<0><<<NB, 256, SCAN_SMEM>>>(Uh, cell_l);
    uxconj_kernel<<<NT*NB, 256, UX_SMEM>>>(Ux, cell_l);
    scan_kernel<1><<<NB, 256, SCAN_SMEM>>>(Uh, cell_l);
    dense_meas_kernel<<<NT*NB, 256>>>(dense_w, dense_l, meas, out);
}

// round 3
// speedup vs baseline: 1.0007x; 1.0007x over previous
#include <cuda_runtime.h>
#include <math.h>

#define NB   64
#define NT   128
#define NIN  300
#define ND   64
#define NC   10
#define BETAC 0.8f

// ---------------- scratch (device globals; no allocations) ----------------
static __device__ float g_u1r[NB*NT*ND];
static __device__ float g_u1i[NB*NT*ND];
static __device__ float g_L1r[(size_t)NT*NB*ND*ND];   // layer outputs (reused for layer 2)
static __device__ float g_L1i[(size_t)NT*NB*ND*ND];
static __device__ float g_ux2r[(size_t)NT*NB*ND*ND];  // lam * Ux X Ux^T for layer 2
static __device__ float g_ux2i[(size_t)NT*NB*ND*ND];

__device__ __forceinline__ float sigmoidf_(float v) { return 1.0f / (1.0f + expf(-v)); }

#define FMA4(acc, s, v)  do { (acc).x = fmaf((s),(v).x,(acc).x); (acc).y = fmaf((s),(v).y,(acc).y); \
                              (acc).z = fmaf((s),(v).z,(acc).z); (acc).w = fmaf((s),(v).w,(acc).w); } while(0)
#define FMA4N(acc, s, v) do { (acc).x = fmaf(-(s),(v).x,(acc).x); (acc).y = fmaf(-(s),(v).y,(acc).y); \
                              (acc).z = fmaf(-(s),(v).z,(acc).z); (acc).w = fmaf(-(s),(v).w,(acc).w); } while(0)

// ---------------- K1: projections + layer-1 x-side (rank-1) ----------------
// blk = b*NT + t, 64 threads (thread = output dim d)
__global__ void proj_kernel(const float* __restrict__ x,
                            const float* __restrict__ amp_w,
                            const float* __restrict__ amp_b,
                            const float* __restrict__ phase_w,
                            const float* __restrict__ phase_b,
                            const float* __restrict__ Ux)
{
    __shared__ float xsh[NIN];
    __shared__ float red[ND];
    __shared__ float ssr[ND], ssi[ND];
    __shared__ float sUxT[ND*65];   // sUxT[e*65+d] = Ux[d][e]
    const int blk = blockIdx.x;
    const int tid = threadIdx.x;
    const float* xrow = x + (size_t)blk * NIN;

    for (int i = tid; i < NIN; i += ND) xsh[i] = xrow[i];
    for (int i = tid; i < ND*ND; i += ND) sUxT[(i & 63)*65 + (i >> 6)] = Ux[i];
    __syncthreads();

    float a = amp_b[tid], p = phase_b[tid];
#pragma unroll 4
    for (int k = 0; k < NIN; k++) {
        float xv = xsh[k];
        a = fmaf(xv, amp_w[k*ND + tid], a);
        p = fmaf(xv, phase_w[k*ND + tid], p);
    }
    red[tid] = a * a;
    __syncthreads();
    if (tid == 0) {
        float s = 0.f;
        for (int i = 0; i < ND; i++) s += red[i];
        red[0] = 1.0f / sqrtf(s);
    }
    __syncthreads();
    float amp = a * red[0];
    ssr[tid] = amp * cosf(p);
    ssi[tid] = amp * sinf(p);
    __syncthreads();

    float ur = 0.f, ui = 0.f;
#pragma unroll 4
    for (int e = 0; e < ND; e++) {
        float u = sUxT[e*65 + tid];       // Ux[tid][e]
        ur = fmaf(u, ssr[e], ur);
        ui = fmaf(u, ssi[e], ui);
    }
    g_u1r[(size_t)blk*ND + tid] = ur;
    g_u1i[(size_t)blk*ND + tid] = ui;
}

// ---------------- K2/K4: recurrent scan (one CTA per batch element) --------
// MODE 0: layer 1 (x-side = rank-1 outer of g_u1), writes g_L1.
// MODE 1: layer 2 (x-side = g_ux2, lam pre-folded), writes g_L1 (reused).
template<int MODE>
__global__ void __launch_bounds__(256, 1) scan_kernel(const float* __restrict__ Uh,
                                                      const float* __restrict__ lam_ptr)
{
    extern __shared__ float sm[];
    float* sUh  = sm;             // [64][64]
    float* sUhT = sm + 4096;      // sUhT[k*64+j] = Uh[j][k]
    float* sHr  = sm + 8192;
    float* sHi  = sm + 12288;
    float* sTr  = sm + 16384;
    float* sTi  = sm + 20480;
    float* sNr  = sm + 24576;
    float* sNi  = sm + 28672;
    __shared__ float tr_s;
    __shared__ float suvr[ND], suvi[ND];

    const int b   = blockIdx.x;
    const int tid = threadIdx.x;
    const int tx = tid & 15, ty = tid >> 4;
    const int i0 = ty * 4;
    const float lam = sigmoidf_(lam_ptr[0]);
    const float oml = 1.0f - lam;

    for (int i = tid; i < ND*ND; i += 256) {
        float v = Uh[i];
        sUh[i] = v;
        sUhT[(i & 63)*64 + (i >> 6)] = v;
        sHr[i] = ((i >> 6) == (i & 63)) ? (1.0f/ND) : 0.0f;
        sHi[i] = 0.0f;
    }
    __syncthreads();

    for (int t = 0; t < NT; t++) {
        if (MODE == 0) {
            if (tid < ND) {
                suvr[tid] = g_u1r[((size_t)b*NT + t)*ND + tid];
                suvi[tid] = g_u1i[((size_t)b*NT + t)*ND + tid];
            }
        }
        // ---- P1: tmp = Uh @ H (both real and imag share A=Uh) ----
        {
            float4 aR[4], aI[4];
#pragma unroll
            for (int r = 0; r < 4; r++) { aR[r] = make_float4(0,0,0,0); aI[r] = make_float4(0,0,0,0); }
            const float4* hr4 = (const float4*)sHr;
            const float4* hi4 = (const float4*)sHi;
#pragma unroll 4
            for (int k = 0; k < ND; k++) {
                float4 br = hr4[k*16 + tx];
                float4 bi = hi4[k*16 + tx];
#pragma unroll
                for (int r = 0; r < 4; r++) {
                    float av = sUh[(i0+r)*64 + k];
                    FMA4(aR[r], av, br);
                    FMA4(aI[r], av, bi);
                }
            }
#pragma unroll
            for (int r = 0; r < 4; r++) {
                ((float4*)sTr)[(i0+r)*16 + tx] = aR[r];
                ((float4*)sTi)[(i0+r)*16 + tx] = aI[r];
            }
        }
        __syncthreads();

        // ---- P2: UH = tmp @ Uh^T ; N = lam*UX + (1-lam)*UH ----
        {
            float4 nR[4], nI[4];
#pragma unroll
            for (int r = 0; r < 4; r++) { nR[r] = make_float4(0,0,0,0); nI[r] = make_float4(0,0,0,0); }
            const float4* uhT4 = (const float4*)sUhT;
#pragma unroll 4
            for (int k = 0; k < ND; k++) {
                float4 b4 = uhT4[k*16 + tx];
#pragma unroll
                for (int r = 0; r < 4; r++) {
                    float ar = sTr[(i0+r)*64 + k];
                    float ai = sTi[(i0+r)*64 + k];
                    FMA4(nR[r], ar, b4);
                    FMA4(nI[r], ai, b4);
                }
            }
            if (MODE == 0) {
                const int j0 = tx * 4;
                float vjr0 = suvr[j0], vjr1 = suvr[j0+1], vjr2 = suvr[j0+2], vjr3 = suvr[j0+3];
                float vji0 = suvi[j0], vji1 = suvi[j0+1], vji2 = suvi[j0+2], vji3 = suvi[j0+3];
#pragma unroll
                for (int r = 0; r < 4; r++) {
                    float uir = suvr[i0+r], uii = suvi[i0+r];
                    nR[r].x = fmaf(oml, nR[r].x, lam*(uir*vjr0 + uii*vji0));
                    nR[r].y = fmaf(oml, nR[r].y, lam*(uir*vjr1 + uii*vji1));
                    nR[r].z = fmaf(oml, nR[r].z, lam*(uir*vjr2 + uii*vji2));
                    nR[r].w = fmaf(oml, nR[r].w, lam*(uir*vjr3 + uii*vji3));
                    nI[r].x = fmaf(oml, nI[r].x, lam*(uii*vjr0 - uir*vji0));
                    nI[r].y = fmaf(oml, nI[r].y, lam*(uii*vjr1 - uir*vji1));
                    nI[r].z = fmaf(oml, nI[r].z, lam*(uii*vjr2 - uir*vji2));
                    nI[r].w = fmaf(oml, nI[r].w, lam*(uii*vjr3 - uir*vji3));
                }
            } else {
                const float4* xr4 = (const float4*)(g_ux2r + ((size_t)t*NB + b)*4096);
                const float4* xi4 = (const float4*)(g_ux2i + ((size_t)t*NB + b)*4096);
#pragma unroll
                for (int r = 0; r < 4; r++) {
                    float4 xr = xr4[(i0+r)*16 + tx];
                    float4 xi = xi4[(i0+r)*16 + tx];
                    nR[r].x = fmaf(oml, nR[r].x, xr.x);
                    nR[r].y = fmaf(oml, nR[r].y, xr.y);
                    nR[r].z = fmaf(oml, nR[r].z, xr.z);
                    nR[r].w = fmaf(oml, nR[r].w, xr.w);
                    nI[r].x = fmaf(oml, nI[r].x, xi.x);
                    nI[r].y = fmaf(oml, nI[r].y, xi.y);
                    nI[r].z = fmaf(oml, nI[r].z, xi.z);
                    nI[r].w = fmaf(oml, nI[r].w, xi.w);
                }
            }
#pragma unroll
            for (int r = 0; r < 4; r++) {
                ((float4*)sNr)[(i0+r)*16 + tx] = nR[r];
                ((float4*)sNi)[(i0+r)*16 + tx] = nI[r];
            }
        }
        if (tid == 0) tr_s = 0.0f;
        __syncthreads();

        // ---- P3: r2 = N_r N_r - N_i N_i ; i2 = N_r N_i + N_i N_r ; activation ----
        {
            float4 cR[4], cI[4];
#pragma unroll
            for (int r = 0; r < 4; r++) { cR[r] = make_float4(0,0,0,0); cI[r] = make_float4(0,0,0,0); }
            const float4* nr4 = (const float4*)sNr;
            const float4* ni4 = (const float4*)sNi;
#pragma unroll 2
            for (int k = 0; k < ND; k++) {
                float4 br = nr4[k*16 + tx];
                float4 bi = ni4[k*16 + tx];
#pragma unroll
                for (int r = 0; r < 4; r++) {
                    float ar = sNr[(i0+r)*64 + k];
                    float ai = sNi[(i0+r)*64 + k];
                    FMA4 (cR[r], ar, br);
                    FMA4N(cR[r], ai, bi);
                    FMA4 (cI[r], ar, bi);
                    FMA4 (cI[r], ai, br);
                }
            }
            if (ty == tx)  // this thread holds 4 diagonal elements of r2
                atomicAdd(&tr_s, cR[0].x + cR[1].y + cR[2].z + cR[3].w);
            __syncthreads();

            const float s  = BETAC / tr_s;
            const float ob = 1.0f - BETAC;
            float4* gr = (float4*)(g_L1r + ((size_t)t*NB + b)*4096);
            float4* gi = (float4*)(g_L1i + ((size_t)t*NB + b)*4096);
#pragma unroll
            for (int r = 0; r < 4; r++) {
                float4 nr = ((const float4*)sNr)[(i0+r)*16 + tx];
                float4 ni = ((const float4*)sNi)[(i0+r)*16 + tx];
                float4 hR, hI;
                hR.x = fmaf(s, cR[r].x, ob*nr.x);  hR.y = fmaf(s, cR[r].y, ob*nr.y);
                hR.z = fmaf(s, cR[r].z, ob*nr.z);  hR.w = fmaf(s, cR[r].w, ob*nr.w);
                hI.x = fmaf(s, cI[r].x, ob*ni.x);  hI.y = fmaf(s, cI[r].y, ob*ni.y);
                hI.z = fmaf(s, cI[r].z, ob*ni.z);  hI.w = fmaf(s, cI[r].w, ob*ni.w);
                ((float4*)sHr)[(i0+r)*16 + tx] = hR;
                ((float4*)sHi)[(i0+r)*16 + tx] = hI;
                gr[(i0+r)*16 + tx] = hR;
                gi[(i0+r)*16 + tx] = hI;
            }
        }
        __syncthreads();
    }
}

// ---------------- K3: layer-2 x-side conjugation (parallel over t,b) -------
// out = lam * Ux @ X @ Ux^T ; blk = t*NB + b
__global__ void __launch_bounds__(256) uxconj_kernel(const float* __restrict__ Ux,
                                                     const float* __restrict__ lam_ptr)
{
    extern __shared__ float sm[];
    float* sUx  = sm;
    float* sUxT = sm + 4096;
    float* sXr  = sm + 8192;
    float* sXi  = sm + 12288;
    float* sTr  = sm + 16384;
    float* sTi  = sm + 20480;
    const int tid = threadIdx.x;
    const int tx = tid & 15, ty = tid >> 4;
    const int i0 = ty * 4;
    const float lam = sigmoidf_(lam_ptr[0]);
    const size_t base = (size_t)blockIdx.x * 4096;

    for (int i = tid; i < ND*ND; i += 256) {
        float v = Ux[i];
        sUx[i] = v;
        sUxT[(i & 63)*64 + (i >> 6)] = v;
        sXr[i] = g_L1r[base + i];
        sXi[i] = g_L1i[base + i];
    }
    __syncthreads();

    // P1: tmp = Ux @ X
    {
        float4 aR[4], aI[4];
#pragma unroll
        for (int r = 0; r < 4; r++) { aR[r] = make_float4(0,0,0,0); aI[r] = make_float4(0,0,0,0); }
        const float4* xr4 = (const float4*)sXr;
        const float4* xi4 = (const float4*)sXi;
#pragma unroll 4
        for (int k = 0; k < ND; k++) {
            float4 br = xr4[k*16 + tx];
            float4 bi = xi4[k*16 + tx];
#pragma unroll
            for (int r = 0; r < 4; r++) {
                float av = sUx[(i0+r)*64 + k];
                FMA4(aR[r], av, br);
                FMA4(aI[r], av, bi);
            }
        }
#pragma unroll
        for (int r = 0; r < 4; r++) {
            ((float4*)sTr)[(i0+r)*16 + tx] = aR[r];
            ((float4*)sTi)[(i0+r)*16 + tx] = aI[r];
        }
    }
    __syncthreads();

    // P2: out = lam * tmp @ Ux^T
    {
        float4 oR[4], oI[4];
#pragma unroll
        for (int r = 0; r < 4; r++) { oR[r] = make_float4(0,0,0,0); oI[r] = make_float4(0,0,0,0); }
        const float4* uxT4 = (const float4*)sUxT;
#pragma unroll 4
        for (int k = 0; k < ND; k++) {
            float4 b4 = uxT4[k*16 + tx];
#pragma unroll
            for (int r = 0; r < 4; r++) {
                float ar = sTr[(i0+r)*64 + k];
                float ai = sTi[(i0+r)*64 + k];
                FMA4(oR[r], ar, b4);
                FMA4(oI[r], ai, b4);
            }
        }
        float4* gr = (float4*)(g_ux2r + base);
        float4* gi = (float4*)(g_ux2i + base);
#pragma unroll
        for (int r = 0; r < 4; r++) {
            float4 vR = oR[r], vI = oI[r];
            vR.x *= lam; vR.y *= lam; vR.z *= lam; vR.w *= lam;
            vI.x *= lam; vI.y *= lam; vI.z *= lam; vI.w *= lam;
            gr[(i0+r)*16 + tx] = vR;
            gi[(i0+r)*16 + tx] = vI;
        }
    }
}

// ---------------- K5: dense + measurement + log (parallel over t,b) --------
__global__ void __launch_bounds__(256) dense_meas_kernel(const float* __restrict__ W,
                                                         const float* __restrict__ dlam_ptr,
                                                         const float* __restrict__ mk,
                                                         float* __restrict__ out)
{
    __shared__ float sRr[ND*ND], sRi[ND*ND];
    __shared__ float sW[ND*NC];
    __shared__ float tmpr[ND*NC], tmpi[ND*NC];
    __shared__ float sgr[NC*NC], sgi[NC*NC];
    __shared__ float svr[NC*NC], svi[NC*NC];
    const int blk = blockIdx.x;     // t*NB + b
    const int tid = threadIdx.x;
    const size_t base = (size_t)blk * 4096;

    for (int i = tid; i < ND*ND; i += 256) { sRr[i] = g_L1r[base + i]; sRi[i] = g_L1i[base + i]; }
    for (int i = tid; i < ND*NC; i += 256) sW[i] = W[i];
    if (tid < NC) {
        float nrm = 0.f;
        for (int c = 0; c < NC; c++) {
            float vr = mk[(tid*NC + c)*2 + 0];
            float vi = mk[(tid*NC + c)*2 + 1];
            nrm += vr*vr + vi*vi;
        }
        float inv = 1.0f / sqrtf(nrm);
        for (int c = 0; c < NC; c++) {
            svr[tid*NC + c] = mk[(tid*NC + c)*2 + 0] * inv;
            svi[tid*NC + c] = mk[(tid*NC + c)*2 + 1] * inv;
        }
    }
    __syncthreads();

    // tmp = rho @ W  [64][10]
    for (int idx = tid; idx < ND*NC; idx += 256) {
        int d = idx / NC, c = idx % NC;
        float ar = 0.f, ai = 0.f;
#pragma unroll 4
        for (int e = 0; e < ND; e++) {
            float w = sW[e*NC + c];
            ar = fmaf(sRr[d*64 + e], w, ar);
            ai = fmaf(sRi[d*64 + e], w, ai);
        }
        tmpr[idx] = ar; tmpi[idx] = ai;
    }
    __syncthreads();

    // sg = W^T @ tmp [10][10], Lambda-mix
    if (tid < NC*NC) {
        int c = tid / NC, f = tid % NC;
        float ar = 0.f, ai = 0.f;
#pragma unroll 4
        for (int d = 0; d < ND; d++) {
            float w = sW[d*NC + c];
            ar = fmaf(w, tmpr[d*NC + f], ar);
            ai = fmaf(w, tmpi[d*NC + f], ai);
        }
        float dlam = sigmoidf_(dlam_ptr[0]);
        ar = dlam * ar + ((c == f) ? (1.0f - dlam) / NC : 0.0f);
        ai = dlam * ai;
        sgr[tid] = ar; sgi[tid] = ai;
    }
    __syncthreads();

    if (tid < NC) {
        float tr = 0.f;
        for (int c = 0; c < NC; c++) tr += sgr[c*NC + c];
        float invtr = 1.0f / tr;
        int k = tid;
        float p = 0.f;
        for (int c = 0; c < NC; c++) {
            float vrc = svr[k*NC + c], vic = svi[k*NC + c];
            for (int d = 0; d < NC; d++) {
                float vrd = svr[k*NC + d], vid = svi[k*NC + d];
                p += (vrc*vrd + vic*vid) * sgr[c*NC + d]
                   + (vic*vrd - vrc*vid) * sgi[c*NC + d];
            }
        }
        p *= invtr;
        int t = blk / NB, b = blk % NB;
        out[((size_t)b*NT + t)*NC + k] = logf(p);
    }
}

// ---------------- launch ----------------
extern "C" void kernel_launch(void* const* d_in, const int* in_sizes, int n_in,
                              void* d_out, int out_size)
{
    const float* x        = (const float*)d_in[0];
    const float* amp_w    = (const float*)d_in[1];
    const float* amp_b    = (const float*)d_in[2];
    const float* phase_w  = (const float*)d_in[3];
    const float* phase_b  = (const float*)d_in[4];
    const float* Ux       = (const float*)d_in[5];
    const float* Uh       = (const float*)d_in[6];
    const float* cell_l   = (const float*)d_in[7];
    const float* dense_w  = (const float*)d_in[8];
    const float* dense_l  = (const float*)d_in[9];
    const float* meas     = (const float*)d_in[10];
    float* out = (float*)d_out;

    const int SCAN_SMEM = 8 * 4096 * 4;   // 128 KB
    const int UX_SMEM   = 6 * 4096 * 4;   // 96 KB
    cudaFuncSetAttribute(scan_kernel<0>, cudaFuncAttributeMaxDynamicSharedMemorySize, SCAN_SMEM);
    cudaFuncSetAttribute(scan_kernel<1>, cudaFuncAttributeMaxDynamicSharedMemorySize, SCAN_SMEM);
    cudaFuncSetAttribute(uxconj_kernel,  cudaFuncAttributeMaxDynamicSharedMemorySize, UX_SMEM);

    proj_kernel<<<NB*NT, ND>>>(x, amp_w, amp_b, phase_w, phase_b, Ux);
    scan_kernel<0><<<NB, 256, SCAN_SMEM>>>(Uh, cell_l);
    uxconj_kernel<<<NT*NB, 256, UX_SMEM>>>(Ux, cell_l);
    scan_kernel<1><<<NB, 256, SCAN_SMEM>>>(Uh, cell_l);
    dense_meas_kernel<<<NT*NB, 256>>>(dense_w, dense_l, meas, out);
}

// round 4
// speedup vs baseline: 1.1345x; 1.1338x over previous
#include <cuda_runtime.h>
#include <math.h>

#define NB   64
#define NT   128
#define NIN  300
#define ND   64
#define NC   10
#define BETAC 0.8f

typedef unsigned long long u64;

// ---------------- scratch (device globals; no allocations) ----------------
static __device__ float g_u1r[NB*NT*ND];
static __device__ float g_u1i[NB*NT*ND];
static __device__ float g_L1r[(size_t)NT*NB*ND*ND];   // layer outputs (reused for layer 2)
static __device__ float g_L1i[(size_t)NT*NB*ND*ND];
static __device__ float g_ux2r[(size_t)NT*NB*ND*ND];  // lam * Ux X Ux^T for layer 2
static __device__ float g_ux2i[(size_t)NT*NB*ND*ND];

__device__ __forceinline__ float sigmoidf_(float v) { return 1.0f / (1.0f + expf(-v)); }

// ---- packed f32x2 helpers (sm_103a) ----
__device__ __forceinline__ u64 pk2(float a) {
    u64 r; asm("mov.b64 %0, {%1, %1};" : "=l"(r) : "f"(a)); return r;
}
__device__ __forceinline__ void fma2(u64 &d, u64 a, u64 b) {
    asm("fma.rn.f32x2 %0, %1, %2, %0;" : "+l"(d) : "l"(a), "l"(b));
}
union UF { ulonglong2 u; float4 f; };

#define GETC(v,kk) ((kk)==0?(v).x:((kk)==1?(v).y:((kk)==2?(v).z:(v).w)))

// ---------------- K1: projections + layer-1 x-side (rank-1) ----------------
__global__ void proj_kernel(const float* __restrict__ x,
                            const float* __restrict__ amp_w,
                            const float* __restrict__ amp_b,
                            const float* __restrict__ phase_w,
                            const float* __restrict__ phase_b,
                            const float* __restrict__ Ux)
{
    __shared__ float xsh[NIN];
    __shared__ float red[ND];
    __shared__ float ssr[ND], ssi[ND];
    __shared__ float sUxT[ND*65];
    const int blk = blockIdx.x;
    const int tid = threadIdx.x;
    const float* xrow = x + (size_t)blk * NIN;

    for (int i = tid; i < NIN; i += ND) xsh[i] = xrow[i];
    for (int i = tid; i < ND*ND; i += ND) sUxT[(i & 63)*65 + (i >> 6)] = Ux[i];
    __syncthreads();

    float a = amp_b[tid], p = phase_b[tid];
#pragma unroll 4
    for (int k = 0; k < NIN; k++) {
        float xv = xsh[k];
        a = fmaf(xv, amp_w[k*ND + tid], a);
        p = fmaf(xv, phase_w[k*ND + tid], p);
    }
    red[tid] = a * a;
    __syncthreads();
    if (tid == 0) {
        float s = 0.f;
        for (int i = 0; i < ND; i++) s += red[i];
        red[0] = 1.0f / sqrtf(s);
    }
    __syncthreads();
    float amp = a * red[0];
    ssr[tid] = amp * cosf(p);
    ssi[tid] = amp * sinf(p);
    __syncthreads();

    float ur = 0.f, ui = 0.f;
#pragma unroll 4
    for (int e = 0; e < ND; e++) {
        float u = sUxT[e*65 + tid];
        ur = fmaf(u, ssr[e], ur);
        ui = fmaf(u, ssi[e], ui);
    }
    g_u1r[(size_t)blk*ND + tid] = ur;
    g_u1i[(size_t)blk*ND + tid] = ui;
}

// ---------------- K2/K4: recurrent scan (one CTA per batch element) --------
template<int MODE>
__global__ void __launch_bounds__(256, 1) scan_kernel(const float* __restrict__ Uh,
                                                      const float* __restrict__ lam_ptr)
{
    extern __shared__ float sm[];
    float* sUh  = sm;             // a operand, P1
    float* sUhT = sm + 4096;      // b operand, P2 (transposed Uh)
    float* sHr  = sm + 8192;
    float* sHi  = sm + 12288;
    float* sTr  = sm + 16384;
    float* sTi  = sm + 20480;
    float* sNr  = sm + 24576;
    float* sNi  = sm + 28672;
    float* sNn  = sm + 32768;     // -N_i, for P3's  -ai*bi  via fma2
    __shared__ float tr_s;
    __shared__ float suvr[ND], suvi[ND];

    const int b   = blockIdx.x;
    const int tid = threadIdx.x;
    const int tx = tid & 15, ty = tid >> 4;
    const int i0 = ty * 4;
    const float lam = sigmoidf_(lam_ptr[0]);
    const float oml = 1.0f - lam;

    for (int i = tid; i < ND*ND; i += 256) {
        float v = Uh[i];
        sUh[i] = v;
        sUhT[(i & 63)*64 + (i >> 6)] = v;
        sHr[i] = ((i >> 6) == (i & 63)) ? (1.0f/ND) : 0.0f;
        sHi[i] = 0.0f;
    }
    __syncthreads();

    for (int t = 0; t < NT; t++) {
        if (MODE == 0) {
            if (tid < ND) {
                suvr[tid] = g_u1r[((size_t)b*NT + t)*ND + tid];
                suvi[tid] = g_u1i[((size_t)b*NT + t)*ND + tid];
            }
        }
        // ---- P1: tmp = Uh @ H (real & imag share A=Uh) ----
        {
            UF aR[4], aI[4];
#pragma unroll
            for (int r = 0; r < 4; r++) { aR[r].f = make_float4(0,0,0,0); aI[r].f = make_float4(0,0,0,0); }
            const ulonglong2* hr2 = (const ulonglong2*)sHr;
            const ulonglong2* hi2 = (const ulonglong2*)sHi;
#pragma unroll 2
            for (int k0 = 0; k0 < ND; k0 += 4) {
                float4 a4[4];
#pragma unroll
                for (int r = 0; r < 4; r++) a4[r] = *(const float4*)&sUh[(i0+r)*64 + k0];
#pragma unroll
                for (int kk = 0; kk < 4; kk++) {
                    ulonglong2 br = hr2[(k0+kk)*16 + tx];
                    ulonglong2 bi = hi2[(k0+kk)*16 + tx];
#pragma unroll
                    for (int r = 0; r < 4; r++) {
                        u64 ap = pk2(GETC(a4[r], kk));
                        fma2(aR[r].u.x, ap, br.x); fma2(aR[r].u.y, ap, br.y);
                        fma2(aI[r].u.x, ap, bi.x); fma2(aI[r].u.y, ap, bi.y);
                    }
                }
            }
#pragma unroll
            for (int r = 0; r < 4; r++) {
                ((float4*)sTr)[(i0+r)*16 + tx] = aR[r].f;
                ((float4*)sTi)[(i0+r)*16 + tx] = aI[r].f;
            }
        }
        __syncthreads();

        // ---- P2: UH = tmp @ Uh^T ; N = lam*UX + (1-lam)*UH ----
        {
            UF nR[4], nI[4];
#pragma unroll
            for (int r = 0; r < 4; r++) { nR[r].f = make_float4(0,0,0,0); nI[r].f = make_float4(0,0,0,0); }
            const ulonglong2* uhT2 = (const ulonglong2*)sUhT;
#pragma unroll 2
            for (int k0 = 0; k0 < ND; k0 += 4) {
                float4 ar4[4], ai4[4];
#pragma unroll
                for (int r = 0; r < 4; r++) {
                    ar4[r] = *(const float4*)&sTr[(i0+r)*64 + k0];
                    ai4[r] = *(const float4*)&sTi[(i0+r)*64 + k0];
                }
#pragma unroll
                for (int kk = 0; kk < 4; kk++) {
                    ulonglong2 b4 = uhT2[(k0+kk)*16 + tx];
#pragma unroll
                    for (int r = 0; r < 4; r++) {
                        u64 arp = pk2(GETC(ar4[r], kk));
                        u64 aip = pk2(GETC(ai4[r], kk));
                        fma2(nR[r].u.x, arp, b4.x); fma2(nR[r].u.y, arp, b4.y);
                        fma2(nI[r].u.x, aip, b4.x); fma2(nI[r].u.y, aip, b4.y);
                    }
                }
            }
            if (MODE == 0) {
                const int j0 = tx * 4;
                float vjr0 = suvr[j0], vjr1 = suvr[j0+1], vjr2 = suvr[j0+2], vjr3 = suvr[j0+3];
                float vji0 = suvi[j0], vji1 = suvi[j0+1], vji2 = suvi[j0+2], vji3 = suvi[j0+3];
#pragma unroll
                for (int r = 0; r < 4; r++) {
                    float uir = suvr[i0+r], uii = suvi[i0+r];
                    nR[r].f.x = fmaf(oml, nR[r].f.x, lam*(uir*vjr0 + uii*vji0));
                    nR[r].f.y = fmaf(oml, nR[r].f.y, lam*(uir*vjr1 + uii*vji1));
                    nR[r].f.z = fmaf(oml, nR[r].f.z, lam*(uir*vjr2 + uii*vji2));
                    nR[r].f.w = fmaf(oml, nR[r].f.w, lam*(uir*vjr3 + uii*vji3));
                    nI[r].f.x = fmaf(oml, nI[r].f.x, lam*(uii*vjr0 - uir*vji0));
                    nI[r].f.y = fmaf(oml, nI[r].f.y, lam*(uii*vjr1 - uir*vji1));
                    nI[r].f.z = fmaf(oml, nI[r].f.z, lam*(uii*vjr2 - uir*vji2));
                    nI[r].f.w = fmaf(oml, nI[r].f.w, lam*(uii*vjr3 - uir*vji3));
                }
            } else {
                const float4* xr4 = (const float4*)(g_ux2r + ((size_t)t*NB + b)*4096);
                const float4* xi4 = (const float4*)(g_ux2i + ((size_t)t*NB + b)*4096);
#pragma unroll
                for (int r = 0; r < 4; r++) {
                    float4 xr = xr4[(i0+r)*16 + tx];
                    float4 xi = xi4[(i0+r)*16 + tx];
                    nR[r].f.x = fmaf(oml, nR[r].f.x, xr.x);
                    nR[r].f.y = fmaf(oml, nR[r].f.y, xr.y);
                    nR[r].f.z = fmaf(oml, nR[r].f.z, xr.z);
                    nR[r].f.w = fmaf(oml, nR[r].f.w, xr.w);
                    nI[r].f.x = fmaf(oml, nI[r].f.x, xi.x);
                    nI[r].f.y = fmaf(oml, nI[r].f.y, xi.y);
                    nI[r].f.z = fmaf(oml, nI[r].f.z, xi.z);
                    nI[r].f.w = fmaf(oml, nI[r].f.w, xi.w);
                }
            }
#pragma unroll
            for (int r = 0; r < 4; r++) {
                float4 ni = nI[r].f;
                float4 nn = make_float4(-ni.x, -ni.y, -ni.z, -ni.w);
                ((float4*)sNr)[(i0+r)*16 + tx] = nR[r].f;
                ((float4*)sNi)[(i0+r)*16 + tx] = ni;
                ((float4*)sNn)[(i0+r)*16 + tx] = nn;
            }
        }
        if (tid == 0) tr_s = 0.0f;
        __syncthreads();

        // ---- P3: r2 = Nr Nr - Ni Ni ; i2 = Nr Ni + Ni Nr ; activation ----
        {
            UF cR[4], cI[4];
#pragma unroll
            for (int r = 0; r < 4; r++) { cR[r].f = make_float4(0,0,0,0); cI[r].f = make_float4(0,0,0,0); }
            const ulonglong2* nr2 = (const ulonglong2*)sNr;
            const ulonglong2* ni2 = (const ulonglong2*)sNi;
            const ulonglong2* nn2 = (const ulonglong2*)sNn;
#pragma unroll 2
            for (int k0 = 0; k0 < ND; k0 += 4) {
                float4 ar4[4], ai4[4];
#pragma unroll
                for (int r = 0; r < 4; r++) {
                    ar4[r] = *(const float4*)&sNr[(i0+r)*64 + k0];
                    ai4[r] = *(const float4*)&sNi[(i0+r)*64 + k0];
                }
#pragma unroll
                for (int kk = 0; kk < 4; kk++) {
                    ulonglong2 br = nr2[(k0+kk)*16 + tx];
                    ulonglong2 bi = ni2[(k0+kk)*16 + tx];
                    ulonglong2 bn = nn2[(k0+kk)*16 + tx];
#pragma unroll
                    for (int r = 0; r < 4; r++) {
                        u64 arp = pk2(GETC(ar4[r], kk));
                        u64 aip = pk2(GETC(ai4[r], kk));
                        fma2(cR[r].u.x, arp, br.x); fma2(cR[r].u.y, arp, br.y);
                        fma2(cR[r].u.x, aip, bn.x); fma2(cR[r].u.y, aip, bn.y);
                        fma2(cI[r].u.x, arp, bi.x); fma2(cI[r].u.y, arp, bi.y);
                        fma2(cI[r].u.x, aip, br.x); fma2(cI[r].u.y, aip, br.y);
                    }
                }
            }
            if (ty == tx)
                atomicAdd(&tr_s, cR[0].f.x + cR[1].f.y + cR[2].f.z + cR[3].f.w);
            __syncthreads();

            const float s  = BETAC / tr_s;
            const float ob = 1.0f - BETAC;
            float4* gr = (float4*)(g_L1r + ((size_t)t*NB + b)*4096);
            float4* gi = (float4*)(g_L1i + ((size_t)t*NB + b)*4096);
#pragma unroll
            for (int r = 0; r < 4; r++) {
                float4 nr = ((const float4*)sNr)[(i0+r)*16 + tx];
                float4 ni = ((const float4*)sNi)[(i0+r)*16 + tx];
                float4 hR, hI;
                hR.x = fmaf(s, cR[r].f.x, ob*nr.x);  hR.y = fmaf(s, cR[r].f.y, ob*nr.y);
                hR.z = fmaf(s, cR[r].f.z, ob*nr.z);  hR.w = fmaf(s, cR[r].f.w, ob*nr.w);
                hI.x = fmaf(s, cI[r].f.x, ob*ni.x);  hI.y = fmaf(s, cI[r].f.y, ob*ni.y);
                hI.z = fmaf(s, cI[r].f.z, ob*ni.z);  hI.w = fmaf(s, cI[r].f.w, ob*ni.w);
                ((float4*)sHr)[(i0+r)*16 + tx] = hR;
                ((float4*)sHi)[(i0+r)*16 + tx] = hI;
                gr[(i0+r)*16 + tx] = hR;
                gi[(i0+r)*16 + tx] = hI;
            }
        }
        __syncthreads();
    }
}

// ---------------- K3: layer-2 x-side conjugation (parallel over t,b) -------
__global__ void __launch_bounds__(256) uxconj_kernel(const float* __restrict__ Ux,
                                                     const float* __restrict__ lam_ptr)
{
    extern __shared__ float sm[];
    float* sUx  = sm;
    float* sUxT = sm + 4096;
    float* sXr  = sm + 8192;
    float* sXi  = sm + 12288;
    float* sTr  = sm + 16384;
    float* sTi  = sm + 20480;
    const int tid = threadIdx.x;
    const int tx = tid & 15, ty = tid >> 4;
    const int i0 = ty * 4;
    const float lam = sigmoidf_(lam_ptr[0]);
    const size_t base = (size_t)blockIdx.x * 4096;

    for (int i = tid; i < ND*ND; i += 256) {
        float v = Ux[i];
        sUx[i] = v;
        sUxT[(i & 63)*64 + (i >> 6)] = v;
        sXr[i] = g_L1r[base + i];
        sXi[i] = g_L1i[base + i];
    }
    __syncthreads();

    // P1: tmp = Ux @ X
    {
        UF aR[4], aI[4];
#pragma unroll
        for (int r = 0; r < 4; r++) { aR[r].f = make_float4(0,0,0,0); aI[r].f = make_float4(0,0,0,0); }
        const ulonglong2* xr2 = (const ulonglong2*)sXr;
        const ulonglong2* xi2 = (const ulonglong2*)sXi;
#pragma unroll 2
        for (int k0 = 0; k0 < ND; k0 += 4) {
            float4 a4[4];
#pragma unroll
            for (int r = 0; r < 4; r++) a4[r] = *(const float4*)&sUx[(i0+r)*64 + k0];
#pragma unroll
            for (int kk = 0; kk < 4; kk++) {
                ulonglong2 br = xr2[(k0+kk)*16 + tx];
                ulonglong2 bi = xi2[(k0+kk)*16 + tx];
#pragma unroll
                for (int r = 0; r < 4; r++) {
                    u64 ap = pk2(GETC(a4[r], kk));
                    fma2(aR[r].u.x, ap, br.x); fma2(aR[r].u.y, ap, br.y);
                    fma2(aI[r].u.x, ap, bi.x); fma2(aI[r].u.y, ap, bi.y);
                }
            }
        }
#pragma unroll
        for (int r = 0; r < 4; r++) {
            ((float4*)sTr)[(i0+r)*16 + tx] = aR[r].f;
            ((float4*)sTi)[(i0+r)*16 + tx] = aI[r].f;
        }
    }
    __syncthreads();

    // P2: out = lam * tmp @ Ux^T
    {
        UF oR[4], oI[4];
#pragma unroll
        for (int r = 0; r < 4; r++) { oR[r].f = make_float4(0,0,0,0); oI[r].f = make_float4(0,0,0,0); }
        const ulonglong2* uxT2 = (const ulonglong2*)sUxT;
#pragma unroll 2
        for (int k0 = 0; k0 < ND; k0 += 4) {
            float4 ar4[4], ai4[4];
#pragma unroll
            for (int r = 0; r < 4; r++) {
                ar4[r] = *(const float4*)&sTr[(i0+r)*64 + k0];
                ai4[r] = *(const float4*)&sTi[(i0+r)*64 + k0];
            }
#pragma unroll
            for (int kk = 0; kk < 4; kk++) {
                ulonglong2 b4 = uxT2[(k0+kk)*16 + tx];
#pragma unroll
                for (int r = 0; r < 4; r++) {
                    u64 arp = pk2(GETC(ar4[r], kk));
                    u64 aip = pk2(GETC(ai4[r], kk));
                    fma2(oR[r].u.x, arp, b4.x); fma2(oR[r].u.y, arp, b4.y);
                    fma2(oI[r].u.x, aip, b4.x); fma2(oI[r].u.y, aip, b4.y);
                }
            }
        }
        float4* gr = (float4*)(g_ux2r + base);
        float4* gi = (float4*)(g_ux2i + base);
#pragma unroll
        for (int r = 0; r < 4; r++) {
            float4 vR = oR[r].f, vI = oI[r].f;
            vR.x *= lam; vR.y *= lam; vR.z *= lam; vR.w *= lam;
            vI.x *= lam; vI.y *= lam; vI.z *= lam; vI.w *= lam;
            gr[(i0+r)*16 + tx] = vR;
            gi[(i0+r)*16 + tx] = vI;
        }
    }
}

// ---------------- K5: dense + measurement + log (parallel over t,b) --------
__global__ void __launch_bounds__(256) dense_meas_kernel(const float* __restrict__ W,
                                                         const float* __restrict__ dlam_ptr,
                                                         const float* __restrict__ mk,
                                                         float* __restrict__ out)
{
    __shared__ float sRr[ND*ND], sRi[ND*ND];
    __shared__ float sW[ND*NC];
    __shared__ float tmpr[ND*NC], tmpi[ND*NC];
    __shared__ float sgr[NC*NC], sgi[NC*NC];
    __shared__ float svr[NC*NC], svi[NC*NC];
    const int blk = blockIdx.x;     // t*NB + b
    const int tid = threadIdx.x;
    const size_t base = (size_t)blk * 4096;

    for (int i = tid; i < ND*ND; i += 256) { sRr[i] = g_L1r[base + i]; sRi[i] = g_L1i[base + i]; }
    for (int i = tid; i < ND*NC; i += 256) sW[i] = W[i];
    if (tid < NC) {
        float nrm = 0.f;
        for (int c = 0; c < NC; c++) {
            float vr = mk[(tid*NC + c)*2 + 0];
            float vi = mk[(tid*NC + c)*2 + 1];
            nrm += vr*vr + vi*vi;
        }
        float inv = 1.0f / sqrtf(nrm);
        for (int c = 0; c < NC; c++) {
            svr[tid*NC + c] = mk[(tid*NC + c)*2 + 0] * inv;
            svi[tid*NC + c] = mk[(tid*NC + c)*2 + 1] * inv;
        }
    }
    __syncthreads();

    for (int idx = tid; idx < ND*NC; idx += 256) {
        int d = idx / NC, c = idx % NC;
        float ar = 0.f, ai = 0.f;
#pragma unroll 4
        for (int e = 0; e < ND; e++) {
            float w = sW[e*NC + c];
            ar = fmaf(sRr[d*64 + e], w, ar);
            ai = fmaf(sRi[d*64 + e], w, ai);
        }
        tmpr[idx] = ar; tmpi[idx] = ai;
    }
    __syncthreads();

    if (tid < NC*NC) {
        int c = tid / NC, f = tid % NC;
        float ar = 0.f, ai = 0.f;
#pragma unroll 4
        for (int d = 0; d < ND; d++) {
            float w = sW[d*NC + c];
            ar = fmaf(w, tmpr[d*NC + f], ar);
            ai = fmaf(w, tmpi[d*NC + f], ai);
        }
        float dlam = sigmoidf_(dlam_ptr[0]);
        ar = dlam * ar + ((c == f) ? (1.0f - dlam) / NC : 0.0f);
        ai = dlam * ai;
        sgr[tid] = ar; sgi[tid] = ai;
    }
    __syncthreads();

    if (tid < NC) {
        float tr = 0.f;
        for (int c = 0; c < NC; c++) tr += sgr[c*NC + c];
        float invtr = 1.0f / tr;
        int k = tid;
        float p = 0.f;
        for (int c = 0; c < NC; c++) {
            float vrc = svr[k*NC + c], vic = svi[k*NC + c];
            for (int d = 0; d < NC; d++) {
                float vrd = svr[k*NC + d], vid = svi[k*NC + d];
                p += (vrc*vrd + vic*vid) * sgr[c*NC + d]
                   + (vic*vrd - vrc*vid) * sgi[c*NC + d];
            }
        }
        p *= invtr;
        int t = blk / NB, b = blk % NB;
        out[((size_t)b*NT + t)*NC + k] = logf(p);
    }
}

// ---------------- launch ----------------
extern "C" void kernel_launch(void* const* d_in, const int* in_sizes, int n_in,
                              void* d_out, int out_size)
{
    const float* x        = (const float*)d_in[0];
    const float* amp_w    = (const float*)d_in[1];
    const float* amp_b    = (const float*)d_in[2];
    const float* phase_w  = (const float*)d_in[3];
    const float* phase_b  = (const float*)d_in[4];
    const float* Ux       = (const float*)d_in[5];
    const float* Uh       = (const float*)d_in[6];
    const float* cell_l   = (const float*)d_in[7];
    const float* dense_w  = (const float*)d_in[8];
    const float* dense_l  = (const float*)d_in[9];
    const float* meas     = (const float*)d_in[10];
    float* out = (float*)d_out;

    const int SCAN_SMEM = 9 * 4096 * 4;   // 144 KB
    const int UX_SMEM   = 6 * 4096 * 4;   // 96 KB
    cudaFuncSetAttribute(scan_kernel<0>, cudaFuncAttributeMaxDynamicSharedMemorySize, SCAN_SMEM);
    cudaFuncSetAttribute(scan_kernel<1>, cudaFuncAttributeMaxDynamicSharedMemorySize, SCAN_SMEM);
    cudaFuncSetAttribute(uxconj_kernel,  cudaFuncAttributeMaxDynamicSharedMemorySize, UX_SMEM);

    proj_kernel<<<NB*NT, ND>>>(x, amp_w, amp_b, phase_w, phase_b, Ux);
    scan_kernel<0><<<NB, 256, SCAN_SMEM>>>(Uh, cell_l);
    uxconj_kernel<<<NT*NB, 256, UX_SMEM>>>(Ux, cell_l);
    scan_kernel<1><<<NB, 256, SCAN_SMEM>>>(Uh, cell_l);
    dense_meas_kernel<<<NT*NB, 256>>>(dense_w, dense_l, meas, out);
}